// round 1
// baseline (speedup 1.0000x reference)
#include <cuda_runtime.h>
#include <cstddef>

// LSTM_824633721296: 2-layer LSTM (B=1024, T=512, I=8, H=64) + FC (O=10)
// Persistent-block design: 128 blocks x 256 threads, 8 batch elements per block.
// All weights resident in SMEM. fp32 FFMA throughout.

#define BT        8       // batch per block
#define NB        128     // blocks (1024/8)
#define NTHREADS  256
#define HID       64
#define NG        256     // 4*H
#define TSTEPS    512
#define IDIM      8
#define ODIM      10

#define W0_STRIDE 76      // 72 cols used (8 x | 64 h), padded: 76 % 32 = 12 -> conflict-free
#define W1_STRIDE 132     // 128 cols used (64 h0 | 64 h1), padded: 132 % 32 = 4 -> conflict-free

// smem layout (floats)
#define OFF_W0    0
#define OFF_W1    (OFF_W0 + 256*W0_STRIDE)           // 19456
#define OFF_G     (OFF_W1 + 256*W1_STRIDE)           // +33792
#define OFF_H0    (OFF_G  + BT*NG)                   // +2048
#define OFF_H1    (OFF_H0 + 2*BT*HID)                // +1024
#define OFF_XS    (OFF_H1 + 2*BT*HID)                // +1024
#define SMEM_FLOATS (OFF_XS + 2*BT*IDIM)             // +128 = 57472 floats = 229888 B

__device__ __forceinline__ float sigm_(float x) {
    // 1/(1+e^-x); safe at extremes (e^-x = inf -> 0, e^-x = 0 -> 1)
    return __fdividef(1.0f, 1.0f + __expf(-x));
}
__device__ __forceinline__ float tanh_(float x) {
    // 1 - 2/(e^{2x}+1); safe at extremes (inf -> 1, 0 -> -1), no NaN
    return 1.0f - __fdividef(2.0f, __expf(2.0f * x) + 1.0f);
}

#define FMA4(acc, av, wv)                         \
    do {                                          \
        acc = fmaf((av).x, (wv).x, acc);          \
        acc = fmaf((av).y, (wv).y, acc);          \
        acc = fmaf((av).z, (wv).z, acc);          \
        acc = fmaf((av).w, (wv).w, acc);          \
    } while (0)

extern __shared__ float smem[];

__global__ void __launch_bounds__(NTHREADS, 1)
lstm_persistent_kernel(const float* __restrict__ x,
                       const float* __restrict__ w_ih0, const float* __restrict__ w_hh0,
                       const float* __restrict__ b_ih0, const float* __restrict__ b_hh0,
                       const float* __restrict__ w_ih1, const float* __restrict__ w_hh1,
                       const float* __restrict__ b_ih1, const float* __restrict__ b_hh1,
                       const float* __restrict__ w_fc,  const float* __restrict__ b_fc,
                       float* __restrict__ out)
{
    float* W0 = smem + OFF_W0;     // [256][76]  (cols 0..7 = w_ih0, 8..71 = w_hh0)
    float* W1 = smem + OFF_W1;     // [256][132] (cols 0..63 = w_ih1, 64..127 = w_hh1)
    float* gates = smem + OFF_G;   // [8][256]
    float* h0s = smem + OFF_H0;    // [2][8][64]
    float* h1s = smem + OFF_H1;    // [2][8][64]
    float* xs  = smem + OFF_XS;    // [2][8][8]

    const int tid = threadIdx.x;
    const int b0  = blockIdx.x * BT;

    // ---- stage weights into SMEM (coalesced global reads) ----
    for (int i = tid; i < 256 * 8;  i += NTHREADS) W0[(i >> 3) * W0_STRIDE + (i & 7)]      = w_ih0[i];
    for (int i = tid; i < 256 * 64; i += NTHREADS) W0[(i >> 6) * W0_STRIDE + 8 + (i & 63)] = w_hh0[i];
    for (int i = tid; i < 256 * 64; i += NTHREADS) W1[(i >> 6) * W1_STRIDE + (i & 63)]     = w_ih1[i];
    for (int i = tid; i < 256 * 64; i += NTHREADS) W1[(i >> 6) * W1_STRIDE + 64 + (i & 63)] = w_hh1[i];
    for (int i = tid; i < 2 * BT * HID; i += NTHREADS) { h0s[i] = 0.0f; h1s[i] = 0.0f; }

    // x for t = 0 into xs buffer 0 (16 threads, 2 float4 per batch row)
    if (tid < 16) {
        int b = tid >> 1, q = tid & 1;
        float4 v = *(const float4*)(x + (size_t)(b0 + b) * TSTEPS * IDIM + q * 4);
        *(float4*)(xs + b * IDIM + q * 4) = v;
    }

    // ---- GEMM thread mapping: rows r0 = tid%128 and r1 = r0+128; 4 batches (tid/128)*4.. ----
    const int r0 = tid & 127;
    const int r1 = r0 + 128;
    const int bb = (tid >> 7) * 4;      // batch sub-base (0 or 4)

    const float bias00 = b_ih0[r0] + b_hh0[r0];
    const float bias01 = b_ih0[r1] + b_hh0[r1];
    const float bias10 = b_ih1[r0] + b_hh1[r0];
    const float bias11 = b_ih1[r1] + b_hh1[r1];

    // ---- elementwise mapping: elem a = (eb, eh), elem b = (eb+4, eh); c state in regs ----
    const int eb = tid >> 6;            // 0..3
    const int eh = tid & 63;
    float c0a = 0.0f, c0b = 0.0f, c1a = 0.0f, c1b = 0.0f;

    __syncthreads();

    const float4* W0q = (const float4*)W0;   // row stride 19 float4
    const float4* W1q = (const float4*)W1;   // row stride 33 float4
    const float4* w0r0 = W0q + r0 * (W0_STRIDE / 4);
    const float4* w0r1 = W0q + r1 * (W0_STRIDE / 4);
    const float4* w1r0 = W1q + r0 * (W1_STRIDE / 4);
    const float4* w1r1 = W1q + r1 * (W1_STRIDE / 4);

    for (int t = 0; t < TSTEPS; t++) {
        const int p  = t & 1;
        const int pn = p ^ 1;

        // prefetch x(t+1) into regs (latency hidden behind GEMMs; stored later)
        float4 xpre = make_float4(0.f, 0.f, 0.f, 0.f);
        const bool doPre = (tid < 16) && (t + 1 < TSTEPS);
        if (doPre) {
            int b = tid >> 1, q = tid & 1;
            xpre = *(const float4*)(x + (size_t)(b0 + b) * TSTEPS * IDIM + (size_t)(t + 1) * IDIM + q * 4);
        }

        float acc0[4], acc1[4];

        // ================= GEMM 0: gates0 = [x_t | h0] @ W0^T + bias =================
        #pragma unroll
        for (int b = 0; b < 4; b++) { acc0[b] = bias00; acc1[b] = bias01; }
        {
            const float4* xq = (const float4*)(xs + p * (BT * IDIM));
            const float4* hq = (const float4*)(h0s + p * (BT * HID));
            #pragma unroll
            for (int q = 0; q < 2; q++) {                 // x part (K=8)
                float4 wv0 = w0r0[q];
                float4 wv1 = w0r1[q];
                #pragma unroll
                for (int b = 0; b < 4; b++) {
                    float4 av = xq[(bb + b) * 2 + q];     // warp-broadcast
                    FMA4(acc0[b], av, wv0);
                    FMA4(acc1[b], av, wv1);
                }
            }
            #pragma unroll
            for (int q = 0; q < 16; q++) {                // h part (K=64)
                float4 wv0 = w0r0[2 + q];
                float4 wv1 = w0r1[2 + q];
                #pragma unroll
                for (int b = 0; b < 4; b++) {
                    float4 av = hq[(bb + b) * 16 + q];    // warp-broadcast
                    FMA4(acc0[b], av, wv0);
                    FMA4(acc1[b], av, wv1);
                }
            }
        }
        #pragma unroll
        for (int b = 0; b < 4; b++) {
            gates[(bb + b) * NG + r0] = acc0[b];
            gates[(bb + b) * NG + r1] = acc1[b];
        }
        __syncthreads();

        // ================= ELEM 0: activations, c0 update, write h0[pn] =================
        {
            float* hdst = h0s + pn * (BT * HID);
            {
                const float* g = gates + eb * NG;
                float iv = sigm_(g[eh]);
                float fv = sigm_(g[64 + eh]);
                float gv = tanh_(g[128 + eh]);
                float ov = sigm_(g[192 + eh]);
                c0a = fv * c0a + iv * gv;
                hdst[eb * HID + eh] = ov * tanh_(c0a);
            }
            {
                const float* g = gates + (eb + 4) * NG;
                float iv = sigm_(g[eh]);
                float fv = sigm_(g[64 + eh]);
                float gv = tanh_(g[128 + eh]);
                float ov = sigm_(g[192 + eh]);
                c0b = fv * c0b + iv * gv;
                hdst[(eb + 4) * HID + eh] = ov * tanh_(c0b);
            }
        }
        __syncthreads();

        // ================= GEMM 1: gates1 = [h0_new | h1] @ W1^T + bias =================
        #pragma unroll
        for (int b = 0; b < 4; b++) { acc0[b] = bias10; acc1[b] = bias11; }
        {
            const float4* h0q = (const float4*)(h0s + pn * (BT * HID));
            const float4* h1q = (const float4*)(h1s + p  * (BT * HID));
            #pragma unroll
            for (int q = 0; q < 16; q++) {                // h0_new part
                float4 wv0 = w1r0[q];
                float4 wv1 = w1r1[q];
                #pragma unroll
                for (int b = 0; b < 4; b++) {
                    float4 av = h0q[(bb + b) * 16 + q];
                    FMA4(acc0[b], av, wv0);
                    FMA4(acc1[b], av, wv1);
                }
            }
            #pragma unroll
            for (int q = 0; q < 16; q++) {                // h1 part
                float4 wv0 = w1r0[16 + q];
                float4 wv1 = w1r1[16 + q];
                #pragma unroll
                for (int b = 0; b < 4; b++) {
                    float4 av = h1q[(bb + b) * 16 + q];
                    FMA4(acc0[b], av, wv0);
                    FMA4(acc1[b], av, wv1);
                }
            }
        }
        #pragma unroll
        for (int b = 0; b < 4; b++) {
            gates[(bb + b) * NG + r0] = acc0[b];
            gates[(bb + b) * NG + r1] = acc1[b];
        }
        // store prefetched x(t+1) into xs[pn] (consumed after the next sync)
        if (doPre) {
            int b = tid >> 1, q = tid & 1;
            *(float4*)(xs + pn * (BT * IDIM) + b * IDIM + q * 4) = xpre;
        }
        __syncthreads();

        // ================= ELEM 1: activations, c1 update, write h1[pn] =================
        {
            float* hdst = h1s + pn * (BT * HID);
            {
                const float* g = gates + eb * NG;
                float iv = sigm_(g[eh]);
                float fv = sigm_(g[64 + eh]);
                float gv = tanh_(g[128 + eh]);
                float ov = sigm_(g[192 + eh]);
                c1a = fv * c1a + iv * gv;
                hdst[eb * HID + eh] = ov * tanh_(c1a);
            }
            {
                const float* g = gates + (eb + 4) * NG;
                float iv = sigm_(g[eh]);
                float fv = sigm_(g[64 + eh]);
                float gv = tanh_(g[128 + eh]);
                float ov = sigm_(g[192 + eh]);
                c1b = fv * c1b + iv * gv;
                hdst[(eb + 4) * HID + eh] = ov * tanh_(c1b);
            }
        }
        __syncthreads();
    }

    // ================= FC: out[b] = h1_final @ w_fc^T + b_fc =================
    // after t=511: p=1 -> final h1 in buffer pn=0
    if (tid < BT * ODIM) {
        int b = tid / ODIM, o = tid % ODIM;
        const float* hrow = h1s + b * HID;   // buffer 0
        const float* wrow = w_fc + o * HID;
        float s = b_fc[o];
        #pragma unroll 16
        for (int k = 0; k < HID; k++) s = fmaf(hrow[k], wrow[k], s);
        out[(size_t)(b0 + b) * ODIM + o] = s;
    }
}

extern "C" void kernel_launch(void* const* d_in, const int* in_sizes, int n_in,
                              void* d_out, int out_size)
{
    (void)in_sizes; (void)n_in; (void)out_size;
    const float* x     = (const float*)d_in[0];
    const float* w_ih0 = (const float*)d_in[1];
    const float* w_hh0 = (const float*)d_in[2];
    const float* b_ih0 = (const float*)d_in[3];
    const float* b_hh0 = (const float*)d_in[4];
    const float* w_ih1 = (const float*)d_in[5];
    const float* w_hh1 = (const float*)d_in[6];
    const float* b_ih1 = (const float*)d_in[7];
    const float* b_hh1 = (const float*)d_in[8];
    const float* w_fc  = (const float*)d_in[9];
    const float* b_fc  = (const float*)d_in[10];

    const size_t smem_bytes = (size_t)SMEM_FLOATS * sizeof(float);
    cudaFuncSetAttribute(lstm_persistent_kernel,
                         cudaFuncAttributeMaxDynamicSharedMemorySize, (int)smem_bytes);
    lstm_persistent_kernel<<<NB, NTHREADS, smem_bytes>>>(
        x, w_ih0, w_hh0, b_ih0, b_hh0, w_ih1, w_hh1, b_ih1, b_hh1, w_fc, b_fc,
        (float*)d_out);
}

// round 2
// speedup vs baseline: 1.0157x; 1.0157x over previous
#include <cuda_runtime.h>
#include <cstddef>

// LSTM_824633721296: 2-layer LSTM (B=1024, T=512, I=8, H=64) + FC (O=10)
// Persistent-block design: 128 blocks x 256 threads, 8 batch elements per block.
// All weights resident in SMEM. Packed fp32x2 FFMA2 (K-packed) for the GEMMs.

#define BT        8       // batch per block
#define NB        128     // blocks (1024/8)
#define NTHREADS  256
#define HID       64
#define NG        256     // 4*H
#define TSTEPS    512
#define IDIM      8
#define ODIM      10

#define W0_STRIDE 76      // 72 cols used (8 x | 64 h), padded: 76 % 32 = 12 -> conflict-free
#define W1_STRIDE 132     // 128 cols used (64 h0 | 64 h1), padded: 132 % 32 = 4 -> conflict-free

// smem layout (floats)
#define OFF_W0    0
#define OFF_W1    (OFF_W0 + 256*W0_STRIDE)           // 19456
#define OFF_G     (OFF_W1 + 256*W1_STRIDE)           // +33792
#define OFF_H0    (OFF_G  + BT*NG)                   // +2048
#define OFF_H1    (OFF_H0 + 2*BT*HID)                // +1024
#define OFF_XS    (OFF_H1 + 2*BT*HID)                // +1024
#define SMEM_FLOATS (OFF_XS + 2*BT*IDIM)             // +128 = 57472 floats = 229888 B

__device__ __forceinline__ float sigm_(float x) {
    // 1/(1+e^-x); safe at extremes (e^-x = inf -> 0, e^-x = 0 -> 1)
    return __fdividef(1.0f, 1.0f + __expf(-x));
}
__device__ __forceinline__ float tanh_(float x) {
    // 1 - 2/(e^{2x}+1); safe at extremes (inf -> 1, 0 -> -1), no NaN
    return 1.0f - __fdividef(2.0f, __expf(2.0f * x) + 1.0f);
}

// Packed f32x2 FMA: acc.{lo,hi} += a.{lo,hi} * w.{lo,hi}  (single SASS FFMA2)
__device__ __forceinline__ void ffma2(unsigned long long& acc,
                                      unsigned long long a,
                                      unsigned long long w) {
    asm("fma.rn.f32x2 %0, %1, %2, %0;" : "+l"(acc) : "l"(a), "l"(w));
}
// Horizontal sum of a packed f32x2 accumulator.
__device__ __forceinline__ float hsum2(unsigned long long v) {
    float lo, hi;
    asm("mov.b64 {%0, %1}, %2;" : "=f"(lo), "=f"(hi) : "l"(v));
    return lo + hi;
}
// (bias, 0.0f) packed initializer
__device__ __forceinline__ unsigned long long packbias(float b) {
    return (unsigned long long)__float_as_uint(b);
}

extern __shared__ float smem[];

__global__ void __launch_bounds__(NTHREADS, 1)
lstm_persistent_kernel(const float* __restrict__ x,
                       const float* __restrict__ w_ih0, const float* __restrict__ w_hh0,
                       const float* __restrict__ b_ih0, const float* __restrict__ b_hh0,
                       const float* __restrict__ w_ih1, const float* __restrict__ w_hh1,
                       const float* __restrict__ b_ih1, const float* __restrict__ b_hh1,
                       const float* __restrict__ w_fc,  const float* __restrict__ b_fc,
                       float* __restrict__ out)
{
    float* W0 = smem + OFF_W0;     // [256][76]  (cols 0..7 = w_ih0, 8..71 = w_hh0)
    float* W1 = smem + OFF_W1;     // [256][132] (cols 0..63 = w_ih1, 64..127 = w_hh1)
    float* gates = smem + OFF_G;   // [8][256]
    float* h0s = smem + OFF_H0;    // [2][8][64]
    float* h1s = smem + OFF_H1;    // [2][8][64]
    float* xs  = smem + OFF_XS;    // [2][8][8]

    const int tid = threadIdx.x;
    const int b0  = blockIdx.x * BT;

    // ---- stage weights into SMEM (coalesced global reads) ----
    for (int i = tid; i < 256 * 8;  i += NTHREADS) W0[(i >> 3) * W0_STRIDE + (i & 7)]      = w_ih0[i];
    for (int i = tid; i < 256 * 64; i += NTHREADS) W0[(i >> 6) * W0_STRIDE + 8 + (i & 63)] = w_hh0[i];
    for (int i = tid; i < 256 * 64; i += NTHREADS) W1[(i >> 6) * W1_STRIDE + (i & 63)]     = w_ih1[i];
    for (int i = tid; i < 256 * 64; i += NTHREADS) W1[(i >> 6) * W1_STRIDE + 64 + (i & 63)] = w_hh1[i];
    for (int i = tid; i < 2 * BT * HID; i += NTHREADS) { h0s[i] = 0.0f; h1s[i] = 0.0f; }

    // x for t = 0 into xs buffer 0 (16 threads, 2 float4 per batch row)
    if (tid < 16) {
        int b = tid >> 1, q = tid & 1;
        float4 v = *(const float4*)(x + (size_t)(b0 + b) * TSTEPS * IDIM + q * 4);
        *(float4*)(xs + b * IDIM + q * 4) = v;
    }

    // ---- GEMM thread mapping: rows r0 = tid%128 and r1 = r0+128; 4 batches (tid/128)*4.. ----
    const int r0 = tid & 127;
    const int r1 = r0 + 128;
    const int bb = (tid >> 7) * 4;      // batch sub-base (0 or 4)

    const float bias00 = b_ih0[r0] + b_hh0[r0];
    const float bias01 = b_ih0[r1] + b_hh0[r1];
    const float bias10 = b_ih1[r0] + b_hh1[r0];
    const float bias11 = b_ih1[r1] + b_hh1[r1];

    // ---- elementwise mapping: elem a = (eb, eh), elem b = (eb+4, eh); c state in regs ----
    const int eb = tid >> 6;            // 0..3
    const int eh = tid & 63;
    float c0a = 0.0f, c0b = 0.0f, c1a = 0.0f, c1b = 0.0f;

    __syncthreads();

    // 16B-vector views of weight rows (each element = 2 packed f32x2 operands)
    const ulonglong2* w0r0 = (const ulonglong2*)(W0 + r0 * W0_STRIDE);
    const ulonglong2* w0r1 = (const ulonglong2*)(W0 + r1 * W0_STRIDE);
    const ulonglong2* w1r0 = (const ulonglong2*)(W1 + r0 * W1_STRIDE);
    const ulonglong2* w1r1 = (const ulonglong2*)(W1 + r1 * W1_STRIDE);

    for (int t = 0; t < TSTEPS; t++) {
        const int p  = t & 1;
        const int pn = p ^ 1;

        // prefetch x(t+1) into regs (latency hidden behind GEMMs; stored later)
        float4 xpre = make_float4(0.f, 0.f, 0.f, 0.f);
        const bool doPre = (tid < 16) && (t + 1 < TSTEPS);
        if (doPre) {
            int b = tid >> 1, q = tid & 1;
            xpre = *(const float4*)(x + (size_t)(b0 + b) * TSTEPS * IDIM + (size_t)(t + 1) * IDIM + q * 4);
        }

        unsigned long long acc0[4], acc1[4];

        // ================= GEMM 0: gates0 = [x_t | h0] @ W0^T + bias =================
        #pragma unroll
        for (int b = 0; b < 4; b++) { acc0[b] = packbias(bias00); acc1[b] = packbias(bias01); }
        {
            const ulonglong2* xq = (const ulonglong2*)(xs + p * (BT * IDIM));
            const ulonglong2* hq = (const ulonglong2*)(h0s + p * (BT * HID));
            #pragma unroll
            for (int q = 0; q < 2; q++) {                 // x part (K=8)
                ulonglong2 wv0 = w0r0[q];
                ulonglong2 wv1 = w0r1[q];
                #pragma unroll
                for (int b = 0; b < 4; b++) {
                    ulonglong2 av = xq[(bb + b) * 2 + q]; // warp-broadcast
                    ffma2(acc0[b], av.x, wv0.x); ffma2(acc0[b], av.y, wv0.y);
                    ffma2(acc1[b], av.x, wv1.x); ffma2(acc1[b], av.y, wv1.y);
                }
            }
            #pragma unroll
            for (int q = 0; q < 16; q++) {                // h part (K=64)
                ulonglong2 wv0 = w0r0[2 + q];
                ulonglong2 wv1 = w0r1[2 + q];
                #pragma unroll
                for (int b = 0; b < 4; b++) {
                    ulonglong2 av = hq[(bb + b) * 16 + q]; // warp-broadcast
                    ffma2(acc0[b], av.x, wv0.x); ffma2(acc0[b], av.y, wv0.y);
                    ffma2(acc1[b], av.x, wv1.x); ffma2(acc1[b], av.y, wv1.y);
                }
            }
        }
        #pragma unroll
        for (int b = 0; b < 4; b++) {
            gates[(bb + b) * NG + r0] = hsum2(acc0[b]);
            gates[(bb + b) * NG + r1] = hsum2(acc1[b]);
        }
        __syncthreads();

        // ================= ELEM 0: activations, c0 update, write h0[pn] =================
        {
            float* hdst = h0s + pn * (BT * HID);
            {
                const float* g = gates + eb * NG;
                float iv = sigm_(g[eh]);
                float fv = sigm_(g[64 + eh]);
                float gv = tanh_(g[128 + eh]);
                float ov = sigm_(g[192 + eh]);
                c0a = fv * c0a + iv * gv;
                hdst[eb * HID + eh] = ov * tanh_(c0a);
            }
            {
                const float* g = gates + (eb + 4) * NG;
                float iv = sigm_(g[eh]);
                float fv = sigm_(g[64 + eh]);
                float gv = tanh_(g[128 + eh]);
                float ov = sigm_(g[192 + eh]);
                c0b = fv * c0b + iv * gv;
                hdst[(eb + 4) * HID + eh] = ov * tanh_(c0b);
            }
        }
        __syncthreads();

        // ================= GEMM 1: gates1 = [h0_new | h1] @ W1^T + bias =================
        #pragma unroll
        for (int b = 0; b < 4; b++) { acc0[b] = packbias(bias10); acc1[b] = packbias(bias11); }
        {
            const ulonglong2* h0q = (const ulonglong2*)(h0s + pn * (BT * HID));
            const ulonglong2* h1q = (const ulonglong2*)(h1s + p  * (BT * HID));
            #pragma unroll
            for (int q = 0; q < 16; q++) {                // h0_new part
                ulonglong2 wv0 = w1r0[q];
                ulonglong2 wv1 = w1r1[q];
                #pragma unroll
                for (int b = 0; b < 4; b++) {
                    ulonglong2 av = h0q[(bb + b) * 16 + q];
                    ffma2(acc0[b], av.x, wv0.x); ffma2(acc0[b], av.y, wv0.y);
                    ffma2(acc1[b], av.x, wv1.x); ffma2(acc1[b], av.y, wv1.y);
                }
            }
            #pragma unroll
            for (int q = 0; q < 16; q++) {                // h1 part
                ulonglong2 wv0 = w1r0[16 + q];
                ulonglong2 wv1 = w1r1[16 + q];
                #pragma unroll
                for (int b = 0; b < 4; b++) {
                    ulonglong2 av = h1q[(bb + b) * 16 + q];
                    ffma2(acc0[b], av.x, wv0.x); ffma2(acc0[b], av.y, wv0.y);
                    ffma2(acc1[b], av.x, wv1.x); ffma2(acc1[b], av.y, wv1.y);
                }
            }
        }
        #pragma unroll
        for (int b = 0; b < 4; b++) {
            gates[(bb + b) * NG + r0] = hsum2(acc0[b]);
            gates[(bb + b) * NG + r1] = hsum2(acc1[b]);
        }
        // store prefetched x(t+1) into xs[pn] (consumed after the next sync)
        if (doPre) {
            int b = tid >> 1, q = tid & 1;
            *(float4*)(xs + pn * (BT * IDIM) + b * IDIM + q * 4) = xpre;
        }
        __syncthreads();

        // ================= ELEM 1: activations, c1 update, write h1[pn] =================
        {
            float* hdst = h1s + pn * (BT * HID);
            {
                const float* g = gates + eb * NG;
                float iv = sigm_(g[eh]);
                float fv = sigm_(g[64 + eh]);
                float gv = tanh_(g[128 + eh]);
                float ov = sigm_(g[192 + eh]);
                c1a = fv * c1a + iv * gv;
                hdst[eb * HID + eh] = ov * tanh_(c1a);
            }
            {
                const float* g = gates + (eb + 4) * NG;
                float iv = sigm_(g[eh]);
                float fv = sigm_(g[64 + eh]);
                float gv = tanh_(g[128 + eh]);
                float ov = sigm_(g[192 + eh]);
                c1b = fv * c1b + iv * gv;
                hdst[(eb + 4) * HID + eh] = ov * tanh_(c1b);
            }
        }
        __syncthreads();
    }

    // ================= FC: out[b] = h1_final @ w_fc^T + b_fc =================
    // after t=511: p=1 -> final h1 in buffer pn=0
    if (tid < BT * ODIM) {
        int b = tid / ODIM, o = tid % ODIM;
        const float* hrow = h1s + b * HID;   // buffer 0
        const float* wrow = w_fc + o * HID;
        float s = b_fc[o];
        #pragma unroll 16
        for (int k = 0; k < HID; k++) s = fmaf(hrow[k], wrow[k], s);
        out[(size_t)(b0 + b) * ODIM + o] = s;
    }
}

extern "C" void kernel_launch(void* const* d_in, const int* in_sizes, int n_in,
                              void* d_out, int out_size)
{
    (void)in_sizes; (void)n_in; (void)out_size;
    const float* x     = (const float*)d_in[0];
    const float* w_ih0 = (const float*)d_in[1];
    const float* w_hh0 = (const float*)d_in[2];
    const float* b_ih0 = (const float*)d_in[3];
    const float* b_hh0 = (const float*)d_in[4];
    const float* w_ih1 = (const float*)d_in[5];
    const float* w_hh1 = (const float*)d_in[6];
    const float* b_ih1 = (const float*)d_in[7];
    const float* b_hh1 = (const float*)d_in[8];
    const float* w_fc  = (const float*)d_in[9];
    const float* b_fc  = (const float*)d_in[10];

    const size_t smem_bytes = (size_t)SMEM_FLOATS * sizeof(float);
    cudaFuncSetAttribute(lstm_persistent_kernel,
                         cudaFuncAttributeMaxDynamicSharedMemorySize, (int)smem_bytes);
    lstm_persistent_kernel<<<NB, NTHREADS, smem_bytes>>>(
        x, w_ih0, w_hh0, b_ih0, b_hh0, w_ih1, w_hh1, b_ih1, b_hh1, w_fc, b_fc,
        (float*)d_out);
}